// round 12
// baseline (speedup 1.0000x reference)
#include <cuda_runtime.h>
#include <cuda_fp16.h>
#include <cstdint>

// Problem constants (fixed by the dataset)
#define NCH   12
#define GD    160
#define GH    160
#define GW    160
#define GVOL  (GD * GH * GW)          // 4,096,000 voxels
#define NPTS  2097152

// Binning: bucket = 2x2x4-cell block, ordered z-major -> bucket order sweeps
// the grid linearly (locality for both L1 sector sharing and DRAM).
#define NBX   (GW / 4)                // 40
#define NBY   (GH / 2)                // 80
#define NBZ   (GD / 2)                // 80
#define NB    (NBX * NBY * NBZ)       // 256,000 buckets (~8 pts each)
#define SBLK  1024
#define NSB   (NB / SBLK)             // 250 scan blocks (exact)

// Interleaved channel-last fp16 grid: [D*H*W, 12] halfs = 24 B/voxel, 98.3 MB.
// +pad voxels: unconditional x0+1 read at last voxel (weight fx==0) and 64B
// aligned-window over-read. Zero-initialized .bss.
__device__ __align__(16) __half g_grid_h[((size_t)GVOL + 8) * NCH];

__device__ int    g_counts[NB];
__device__ int    g_offs[NB];
__device__ int    g_bsums[NSB];
__device__ float4 g_sorted[NPTS];     // 32 MB: (x, y, z, bitcast(orig index))

// ---------------------------------------------------------------------------
// Pass 1: transpose+convert [C, D, H, W] fp32 -> [D*H*W, C] fp16.
// One thread = TWO consecutive voxels (12x LDG.64 reads, 3x STG.128 writes).
// ---------------------------------------------------------------------------
__global__ void __launch_bounds__(256) convert_cl_kernel(const float* __restrict__ grid) {
    int t = blockIdx.x * blockDim.x + threadIdx.x;
    int v = t * 2;
    if (v >= GVOL) return;

    __half h[2 * NCH];
#pragma unroll
    for (int c = 0; c < NCH; c++) {
        float2 f = __ldcs(reinterpret_cast<const float2*>(grid + (size_t)c * GVOL + v));
        h[c]       = __float2half(f.x);
        h[NCH + c] = __float2half(f.y);
    }

    uint4* dst = reinterpret_cast<uint4*>(g_grid_h + (size_t)v * NCH);
    const uint4* s = reinterpret_cast<const uint4*>(h);
    dst[0] = s[0];
    dst[1] = s[1];
    dst[2] = s[2];
}

// ---------------------------------------------------------------------------
// Shared coordinate -> bucket mapping (identical in hist/scatter).
// ---------------------------------------------------------------------------
__device__ __forceinline__ int point_bucket(
    float p0, float p1, float p2,
    const float* __restrict__ xyz_min,
    const float* __restrict__ xyz_max)
{
    float mn0 = __ldg(xyz_min + 0), mn1 = __ldg(xyz_min + 1), mn2 = __ldg(xyz_min + 2);
    float mx0 = __ldg(xyz_max + 0), mx1 = __ldg(xyz_max + 1), mx2 = __ldg(xyz_max + 2);
    float u0 = (p0 - mn0) / (mx0 - mn0);
    float u1 = (p1 - mn1) / (mx1 - mn1);
    float u2 = (p2 - mn2) / (mx2 - mn2);
    float px = u2 * (float)(GW - 1);
    float py = u1 * (float)(GH - 1);
    float pz = u0 * (float)(GD - 1);
    int x0 = min(max((int)floorf(px), 0), GW - 1);
    int y0 = min(max((int)floorf(py), 0), GH - 1);
    int z0 = min(max((int)floorf(pz), 0), GD - 1);
    return ((z0 >> 1) * NBY + (y0 >> 1)) * NBX + (x0 >> 2);
}

// --------------------------- binning pipeline ------------------------------
__global__ void __launch_bounds__(256) zero_counts_kernel() {
    int i = blockIdx.x * blockDim.x + threadIdx.x;
    if (i < NB) g_counts[i] = 0;
}

__global__ void __launch_bounds__(256) hist_kernel(
    const float* __restrict__ xyz,
    const float* __restrict__ xyz_min,
    const float* __restrict__ xyz_max, int n)
{
    int i = blockIdx.x * blockDim.x + threadIdx.x;
    if (i >= n) return;
    float p0 = __ldcs(xyz + 3 * (size_t)i + 0);
    float p1 = __ldcs(xyz + 3 * (size_t)i + 1);
    float p2 = __ldcs(xyz + 3 * (size_t)i + 2);
    atomicAdd(&g_counts[point_bucket(p0, p1, p2, xyz_min, xyz_max)], 1);
}

__global__ void __launch_bounds__(SBLK) scan_block_kernel() {
    __shared__ int s[SBLK];
    int t = threadIdx.x;
    int i = blockIdx.x * SBLK + t;
    int v = g_counts[i];
    s[t] = v;
    __syncthreads();
#pragma unroll
    for (int off = 1; off < SBLK; off <<= 1) {
        int x = (t >= off) ? s[t - off] : 0;
        __syncthreads();
        s[t] += x;
        __syncthreads();
    }
    g_offs[i] = s[t] - v;                          // exclusive within block
    if (t == SBLK - 1) g_bsums[blockIdx.x] = s[t]; // block total
}

__global__ void __launch_bounds__(256) scan_bsums_kernel() {
    __shared__ int s[256];
    int t = threadIdx.x;
    int v = (t < NSB) ? g_bsums[t] : 0;
    s[t] = v;
    __syncthreads();
#pragma unroll
    for (int off = 1; off < 256; off <<= 1) {
        int x = (t >= off) ? s[t - off] : 0;
        __syncthreads();
        s[t] += x;
        __syncthreads();
    }
    if (t < NSB) g_bsums[t] = s[t] - v;            // exclusive block offsets
}

__global__ void __launch_bounds__(256) add_bsums_kernel() {
    int i = blockIdx.x * blockDim.x + threadIdx.x;
    if (i < NB) g_offs[i] += g_bsums[i >> 10];     // SBLK == 1024
}

__global__ void __launch_bounds__(256) scatter_kernel(
    const float* __restrict__ xyz,
    const float* __restrict__ xyz_min,
    const float* __restrict__ xyz_max, int n)
{
    int i = blockIdx.x * blockDim.x + threadIdx.x;
    if (i >= n) return;
    float p0 = __ldcs(xyz + 3 * (size_t)i + 0);
    float p1 = __ldcs(xyz + 3 * (size_t)i + 1);
    float p2 = __ldcs(xyz + 3 * (size_t)i + 2);
    int b = point_bucket(p0, p1, p2, xyz_min, xyz_max);
    int pos = atomicAdd(&g_offs[b], 1);
    g_sorted[pos] = make_float4(p0, p1, p2, __int_as_float(i));
}

// ---------------------------------------------------------------------------
// Sample pass: points in bucket order -> warp lanes hit adjacent voxels ->
// gather sectors are SHARED across lanes (L1 sector-wavefront wall drops)
// and the grid is swept nearly linearly (DRAM ~= one cold pass).
// Gathers via 16B-aligned 64B window = 4x LDG.128 per corner-pair.
// ---------------------------------------------------------------------------
__device__ __forceinline__ float2 u2f2(unsigned u) {
    __half2 h = *reinterpret_cast<__half2*>(&u);
    return __half22float2(h);
}

__global__ void __launch_bounds__(256, 4) trilinear_sample_sorted_kernel(
    const float* __restrict__ xyz_min,
    const float* __restrict__ xyz_max,
    float* __restrict__ out,
    int n)
{
    int j = blockIdx.x * blockDim.x + threadIdx.x;
    if (j >= n) return;

    float4 sp = __ldcs(&g_sorted[j]);
    float p0 = sp.x, p1 = sp.y, p2 = sp.z;
    int orig = __float_as_int(sp.w);

    float mn0 = __ldg(xyz_min + 0), mn1 = __ldg(xyz_min + 1), mn2 = __ldg(xyz_min + 2);
    float mx0 = __ldg(xyz_max + 0), mx1 = __ldg(xyz_max + 1), mx2 = __ldg(xyz_max + 2);

    float u0 = (p0 - mn0) / (mx0 - mn0);
    float u1 = (p1 - mn1) / (mx1 - mn1);
    float u2 = (p2 - mn2) / (mx2 - mn2);

    // px indexes W (from u2), py indexes H (from u1), pz indexes D (from u0)
    float px = u2 * (float)(GW - 1);
    float py = u1 * (float)(GH - 1);
    float pz = u0 * (float)(GD - 1);

    float xf = floorf(px), yf = floorf(py), zf = floorf(pz);
    float fx = px - xf,    fy = py - yf,    fz = pz - zf;

    int x0 = min(max((int)xf, 0), GW - 1);
    int y0 = min(max((int)yf, 0), GH - 1);
    int z0 = min(max((int)zf, 0), GD - 1);
    int y1 = min(y0 + 1, GH - 1);
    int z1 = min(z0 + 1, GD - 1);

    float wx0 = 1.0f - fx, wx1 = fx;
    float wy0 = 1.0f - fy, wy1 = fy;
    float wz0 = 1.0f - fz, wz1 = fz;

    float wp[4];
    wp[0] = wz0 * wy0;
    wp[1] = wz0 * wy1;
    wp[2] = wz1 * wy0;
    wp[3] = wz1 * wy1;

    int vidx[4];
    vidx[0] = (z0 * GH + y0) * GW + x0;
    vidx[1] = (z0 * GH + y1) * GW + x0;
    vidx[2] = (z1 * GH + y0) * GW + x0;
    vidx[3] = (z1 * GH + y1) * GW + x0;

    const char* gbase = reinterpret_cast<const char*>(g_grid_h);

    float acc[NCH];
#pragma unroll
    for (int c = 0; c < NCH; c++) acc[c] = 0.0f;

#pragma unroll
    for (int pb = 0; pb < 4; pb += 2) {
        uint4 W[8];
        bool  sh[2];
#pragma unroll
        for (int t = 0; t < 2; t++) {
            int B = vidx[pb + t] * 24;           // byte offset; B mod 16 in {0,8}
            const uint4* q = reinterpret_cast<const uint4*>(gbase + (B & ~15));
            sh[t] = (B & 8) != 0;
            W[t * 4 + 0] = __ldg(q + 0);
            W[t * 4 + 1] = __ldg(q + 1);
            W[t * 4 + 2] = __ldg(q + 2);
            W[t * 4 + 3] = __ldg(q + 3);
        }

#pragma unroll
        for (int t = 0; t < 2; t++) {
            int p = pb + t;
            float w0 = wp[p] * wx0;
            float w1 = wp[p] * wx1;

            unsigned wd[16];
            wd[0]  = W[t*4+0].x; wd[1]  = W[t*4+0].y; wd[2]  = W[t*4+0].z; wd[3]  = W[t*4+0].w;
            wd[4]  = W[t*4+1].x; wd[5]  = W[t*4+1].y; wd[6]  = W[t*4+1].z; wd[7]  = W[t*4+1].w;
            wd[8]  = W[t*4+2].x; wd[9]  = W[t*4+2].y; wd[10] = W[t*4+2].z; wd[11] = W[t*4+2].w;
            wd[12] = W[t*4+3].x; wd[13] = W[t*4+3].y; wd[14] = W[t*4+3].z; wd[15] = W[t*4+3].w;

            unsigned u[12];
#pragma unroll
            for (int k = 0; k < 12; k++)
                u[k] = sh[t] ? wd[k + 2] : wd[k];

            // u[0..5] = x0 ch0-11 (half2 each), u[6..11] = x0+1 ch0-11
#pragma unroll
            for (int jj = 0; jj < 6; jj++) {
                float2 a = u2f2(u[jj]);
                float2 b = u2f2(u[6 + jj]);
                acc[2*jj]   = fmaf(w0, a.x, fmaf(w1, b.x, acc[2*jj]));
                acc[2*jj+1] = fmaf(w0, a.y, fmaf(w1, b.y, acc[2*jj+1]));
            }
        }
    }

    // out is [N, 12] row-major; scatter to the point's original row.
    float4* o = reinterpret_cast<float4*>(out + (size_t)orig * NCH);
    __stcs(o + 0, make_float4(acc[0], acc[1], acc[2],  acc[3]));
    __stcs(o + 1, make_float4(acc[4], acc[5], acc[6],  acc[7]));
    __stcs(o + 2, make_float4(acc[8], acc[9], acc[10], acc[11]));
}

extern "C" void kernel_launch(void* const* d_in, const int* in_sizes, int n_in,
                              void* d_out, int out_size) {
    const float* xyz     = (const float*)d_in[0];  // [N, 3]
    const float* grid    = (const float*)d_in[1];  // [1, 12, 160, 160, 160]
    const float* xyz_min = (const float*)d_in[2];  // [3]
    const float* xyz_max = (const float*)d_in[3];  // [3]
    float* out = (float*)d_out;                    // [N, 12]

    int n = in_sizes[0] / 3;
    int pt_blocks = (n + 255) / 256;

    {
        int blocks = (GVOL / 2 + 255) / 256;
        convert_cl_kernel<<<blocks, 256>>>(grid);
    }
    zero_counts_kernel<<<(NB + 255) / 256, 256>>>();
    hist_kernel<<<pt_blocks, 256>>>(xyz, xyz_min, xyz_max, n);
    scan_block_kernel<<<NSB, SBLK>>>();
    scan_bsums_kernel<<<1, 256>>>();
    add_bsums_kernel<<<(NB + 255) / 256, 256>>>();
    scatter_kernel<<<pt_blocks, 256>>>(xyz, xyz_min, xyz_max, n);
    trilinear_sample_sorted_kernel<<<pt_blocks, 256>>>(xyz_min, xyz_max, out, n);
}

// round 14
// speedup vs baseline: 1.0663x; 1.0663x over previous
#include <cuda_runtime.h>
#include <cuda_fp16.h>
#include <cstdint>

// Problem constants (fixed by the dataset)
#define NCH   12
#define GD    160
#define GH    160
#define GW    160
#define GVOL  (GD * GH * GW)          // 4,096,000 voxels
#define NPTS  2097152

// Row-coherent binning: bucket = (z0, y0, x0>>3). Consecutive buckets share
// the same (z0, y0) row -> a warp's 32 sorted points gather from the SAME
// 4 row segments -> gather sectors shared across lanes.
#define NXB   (GW / 8)                // 20 x-blocks
#define NB    (GD * GH * NXB)         // 512,000 buckets (~4 pts each)
#define SBLK  1024
#define NSB   (NB / SBLK)             // 500 scan blocks (exact)

// Interleaved channel-last fp16 grid: [D*H*W, 12] halfs = 24 B/voxel, 98.3 MB.
// +pad voxels: unconditional x0+1 read at last voxel (weight fx==0) and 64B
// aligned-window over-read. Zero-initialized .bss.
__device__ __align__(16) __half g_grid_h[((size_t)GVOL + 8) * NCH];

__device__ int    g_counts[NB];
__device__ int    g_offs[NB];
__device__ int    g_bsums[NSB];
__device__ float4 g_sorted[NPTS];     // 32 MB: (x, y, z, bitcast(orig index))

// ---------------------------------------------------------------------------
// Pass 1: transpose+convert [C, D, H, W] fp32 -> [D*H*W, C] fp16.
// One thread = TWO consecutive voxels (12x LDG.64 reads, 3x STG.128 writes).
// ---------------------------------------------------------------------------
__global__ void __launch_bounds__(256) convert_cl_kernel(const float* __restrict__ grid) {
    int t = blockIdx.x * blockDim.x + threadIdx.x;
    int v = t * 2;
    if (v >= GVOL) return;

    __half h[2 * NCH];
#pragma unroll
    for (int c = 0; c < NCH; c++) {
        float2 f = __ldcs(reinterpret_cast<const float2*>(grid + (size_t)c * GVOL + v));
        h[c]       = __float2half(f.x);
        h[NCH + c] = __float2half(f.y);
    }

    uint4* dst = reinterpret_cast<uint4*>(g_grid_h + (size_t)v * NCH);
    const uint4* s = reinterpret_cast<const uint4*>(h);
    dst[0] = s[0];
    dst[1] = s[1];
    dst[2] = s[2];
}

// ---------------------------------------------------------------------------
// Coordinate -> bucket (identical in hist/scatter).
// ---------------------------------------------------------------------------
__device__ __forceinline__ int point_bucket(
    float p0, float p1, float p2,
    const float* __restrict__ xyz_min,
    const float* __restrict__ xyz_max)
{
    float mn0 = __ldg(xyz_min + 0), mn1 = __ldg(xyz_min + 1), mn2 = __ldg(xyz_min + 2);
    float mx0 = __ldg(xyz_max + 0), mx1 = __ldg(xyz_max + 1), mx2 = __ldg(xyz_max + 2);
    float u0 = (p0 - mn0) / (mx0 - mn0);
    float u1 = (p1 - mn1) / (mx1 - mn1);
    float u2 = (p2 - mn2) / (mx2 - mn2);
    float px = u2 * (float)(GW - 1);
    float py = u1 * (float)(GH - 1);
    float pz = u0 * (float)(GD - 1);
    int x0 = min(max((int)floorf(px), 0), GW - 1);
    int y0 = min(max((int)floorf(py), 0), GH - 1);
    int z0 = min(max((int)floorf(pz), 0), GD - 1);
    return (z0 * GH + y0) * NXB + (x0 >> 3);
}

// --------------------------- binning pipeline ------------------------------
__global__ void __launch_bounds__(256) zero_counts_kernel() {
    int i = blockIdx.x * blockDim.x + threadIdx.x;
    if (i < NB) g_counts[i] = 0;
}

__global__ void __launch_bounds__(256) hist_kernel(
    const float* __restrict__ xyz,
    const float* __restrict__ xyz_min,
    const float* __restrict__ xyz_max, int n)
{
    int i = blockIdx.x * blockDim.x + threadIdx.x;
    if (i >= n) return;
    float p0 = __ldcs(xyz + 3 * (size_t)i + 0);
    float p1 = __ldcs(xyz + 3 * (size_t)i + 1);
    float p2 = __ldcs(xyz + 3 * (size_t)i + 2);
    atomicAdd(&g_counts[point_bucket(p0, p1, p2, xyz_min, xyz_max)], 1);
}

// Shuffle-based block scan: 1024 threads, 3 barriers total.
__global__ void __launch_bounds__(SBLK) scan_block_kernel() {
    __shared__ int wsum[32];
    int t = threadIdx.x;
    int lane = t & 31, wid = t >> 5;
    int i = blockIdx.x * SBLK + t;
    int v = g_counts[i];

    int x = v;                                   // warp inclusive scan
#pragma unroll
    for (int off = 1; off < 32; off <<= 1) {
        int y = __shfl_up_sync(0xffffffffu, x, off);
        if (lane >= off) x += y;
    }
    if (lane == 31) wsum[wid] = x;
    __syncthreads();
    if (t < 32) {                                // scan the 32 warp sums
        int s = wsum[t];
#pragma unroll
        for (int off = 1; off < 32; off <<= 1) {
            int y = __shfl_up_sync(0xffffffffu, s, off);
            if (t >= off) s += y;
        }
        wsum[t] = s;
    }
    __syncthreads();
    int base = (wid > 0) ? wsum[wid - 1] : 0;
    int incl = base + x;
    g_offs[i] = incl - v;                        // exclusive within block
    if (t == SBLK - 1) g_bsums[blockIdx.x] = incl;
}

// Scan 500 block sums with one 512-thread block.
__global__ void __launch_bounds__(512) scan_bsums_kernel() {
    __shared__ int wsum[16];
    int t = threadIdx.x;
    int lane = t & 31, wid = t >> 5;
    int v = (t < NSB) ? g_bsums[t] : 0;

    int x = v;
#pragma unroll
    for (int off = 1; off < 32; off <<= 1) {
        int y = __shfl_up_sync(0xffffffffu, x, off);
        if (lane >= off) x += y;
    }
    if (lane == 31) wsum[wid] = x;
    __syncthreads();
    if (t < 16) {
        int s = wsum[t];
#pragma unroll
        for (int off = 1; off < 16; off <<= 1) {
            int y = __shfl_up_sync(0x0000ffffu, s, off);
            if (t >= off) s += y;
        }
        wsum[t] = s;
    }
    __syncthreads();
    int base = (wid > 0) ? wsum[wid - 1] : 0;
    if (t < NSB) g_bsums[t] = base + x - v;      // exclusive block offsets
}

__global__ void __launch_bounds__(256) add_bsums_kernel() {
    int i = blockIdx.x * blockDim.x + threadIdx.x;
    if (i < NB) g_offs[i] += g_bsums[i >> 10];   // SBLK == 1024
}

__global__ void __launch_bounds__(256) scatter_kernel(
    const float* __restrict__ xyz,
    const float* __restrict__ xyz_min,
    const float* __restrict__ xyz_max, int n)
{
    int i = blockIdx.x * blockDim.x + threadIdx.x;
    if (i >= n) return;
    float p0 = __ldcs(xyz + 3 * (size_t)i + 0);
    float p1 = __ldcs(xyz + 3 * (size_t)i + 1);
    float p2 = __ldcs(xyz + 3 * (size_t)i + 2);
    int b = point_bucket(p0, p1, p2, xyz_min, xyz_max);
    int pos = atomicAdd(&g_offs[b], 1);
    g_sorted[pos] = make_float4(p0, p1, p2, __int_as_float(i));
}

// ---------------------------------------------------------------------------
// Sample pass: points in row-coherent sorted order. A warp's lanes gather
// from the same 4 row segments -> sectors shared across lanes (L1 wall drops
// ~5x) and the grid is swept near-linearly (gather DRAM ~= one cold pass).
// ---------------------------------------------------------------------------
__device__ __forceinline__ float2 u2f2(unsigned u) {
    __half2 h = *reinterpret_cast<__half2*>(&u);
    return __half22float2(h);
}

__global__ void __launch_bounds__(256, 4) trilinear_sample_sorted_kernel(
    const float* __restrict__ xyz_min,
    const float* __restrict__ xyz_max,
    float* __restrict__ out,
    int n)
{
    int j = blockIdx.x * blockDim.x + threadIdx.x;
    if (j >= n) return;

    float4 sp = __ldcs(&g_sorted[j]);
    float p0 = sp.x, p1 = sp.y, p2 = sp.z;
    int orig = __float_as_int(sp.w);

    float mn0 = __ldg(xyz_min + 0), mn1 = __ldg(xyz_min + 1), mn2 = __ldg(xyz_min + 2);
    float mx0 = __ldg(xyz_max + 0), mx1 = __ldg(xyz_max + 1), mx2 = __ldg(xyz_max + 2);

    float u0 = (p0 - mn0) / (mx0 - mn0);
    float u1 = (p1 - mn1) / (mx1 - mn1);
    float u2 = (p2 - mn2) / (mx2 - mn2);

    // px indexes W (from u2), py indexes H (from u1), pz indexes D (from u0)
    float px = u2 * (float)(GW - 1);
    float py = u1 * (float)(GH - 1);
    float pz = u0 * (float)(GD - 1);

    float xf = floorf(px), yf = floorf(py), zf = floorf(pz);
    float fx = px - xf,    fy = py - yf,    fz = pz - zf;

    int x0 = min(max((int)xf, 0), GW - 1);
    int y0 = min(max((int)yf, 0), GH - 1);
    int z0 = min(max((int)zf, 0), GD - 1);
    int y1 = min(y0 + 1, GH - 1);
    int z1 = min(z0 + 1, GD - 1);

    float wx0 = 1.0f - fx, wx1 = fx;
    float wy0 = 1.0f - fy, wy1 = fy;
    float wz0 = 1.0f - fz, wz1 = fz;

    float wp[4];
    wp[0] = wz0 * wy0;
    wp[1] = wz0 * wy1;
    wp[2] = wz1 * wy0;
    wp[3] = wz1 * wy1;

    int vidx[4];
    vidx[0] = (z0 * GH + y0) * GW + x0;
    vidx[1] = (z0 * GH + y1) * GW + x0;
    vidx[2] = (z1 * GH + y0) * GW + x0;
    vidx[3] = (z1 * GH + y1) * GW + x0;

    const char* gbase = reinterpret_cast<const char*>(g_grid_h);

    float acc[NCH];
#pragma unroll
    for (int c = 0; c < NCH; c++) acc[c] = 0.0f;

#pragma unroll
    for (int pb = 0; pb < 4; pb += 2) {
        uint4 W[8];
        bool  sh[2];
#pragma unroll
        for (int t = 0; t < 2; t++) {
            int B = vidx[pb + t] * 24;           // byte offset; B mod 16 in {0,8}
            const uint4* q = reinterpret_cast<const uint4*>(gbase + (B & ~15));
            sh[t] = (B & 8) != 0;
            W[t * 4 + 0] = __ldg(q + 0);
            W[t * 4 + 1] = __ldg(q + 1);
            W[t * 4 + 2] = __ldg(q + 2);
            W[t * 4 + 3] = __ldg(q + 3);
        }

#pragma unroll
        for (int t = 0; t < 2; t++) {
            int p = pb + t;
            float w0 = wp[p] * wx0;
            float w1 = wp[p] * wx1;

            unsigned wd[16];
            wd[0]  = W[t*4+0].x; wd[1]  = W[t*4+0].y; wd[2]  = W[t*4+0].z; wd[3]  = W[t*4+0].w;
            wd[4]  = W[t*4+1].x; wd[5]  = W[t*4+1].y; wd[6]  = W[t*4+1].z; wd[7]  = W[t*4+1].w;
            wd[8]  = W[t*4+2].x; wd[9]  = W[t*4+2].y; wd[10] = W[t*4+2].z; wd[11] = W[t*4+2].w;
            wd[12] = W[t*4+3].x; wd[13] = W[t*4+3].y; wd[14] = W[t*4+3].z; wd[15] = W[t*4+3].w;

            unsigned u[12];
#pragma unroll
            for (int k = 0; k < 12; k++)
                u[k] = sh[t] ? wd[k + 2] : wd[k];

            // u[0..5] = x0 ch0-11 (half2 each), u[6..11] = x0+1 ch0-11
#pragma unroll
            for (int jj = 0; jj < 6; jj++) {
                float2 a = u2f2(u[jj]);
                float2 b = u2f2(u[6 + jj]);
                acc[2*jj]   = fmaf(w0, a.x, fmaf(w1, b.x, acc[2*jj]));
                acc[2*jj+1] = fmaf(w0, a.y, fmaf(w1, b.y, acc[2*jj+1]));
            }
        }
    }

    // out is [N, 12] row-major; scatter to the point's original row.
    float4* o = reinterpret_cast<float4*>(out + (size_t)orig * NCH);
    __stcs(o + 0, make_float4(acc[0], acc[1], acc[2],  acc[3]));
    __stcs(o + 1, make_float4(acc[4], acc[5], acc[6],  acc[7]));
    __stcs(o + 2, make_float4(acc[8], acc[9], acc[10], acc[11]));
}

extern "C" void kernel_launch(void* const* d_in, const int* in_sizes, int n_in,
                              void* d_out, int out_size) {
    const float* xyz     = (const float*)d_in[0];  // [N, 3]
    const float* grid    = (const float*)d_in[1];  // [1, 12, 160, 160, 160]
    const float* xyz_min = (const float*)d_in[2];  // [3]
    const float* xyz_max = (const float*)d_in[3];  // [3]
    float* out = (float*)d_out;                    // [N, 12]

    int n = in_sizes[0] / 3;
    int pt_blocks = (n + 255) / 256;

    {
        int blocks = (GVOL / 2 + 255) / 256;
        convert_cl_kernel<<<blocks, 256>>>(grid);
    }
    zero_counts_kernel<<<(NB + 255) / 256, 256>>>();
    hist_kernel<<<pt_blocks, 256>>>(xyz, xyz_min, xyz_max, n);
    scan_block_kernel<<<NSB, SBLK>>>();
    scan_bsums_kernel<<<1, 512>>>();
    add_bsums_kernel<<<(NB + 255) / 256, 256>>>();
    scatter_kernel<<<pt_blocks, 256>>>(xyz, xyz_min, xyz_max, n);
    trilinear_sample_sorted_kernel<<<pt_blocks, 256>>>(xyz_min, xyz_max, out, n);
}

// round 15
// speedup vs baseline: 1.4644x; 1.3733x over previous
#include <cuda_runtime.h>
#include <cuda_fp16.h>
#include <cstdint>

// Problem constants (fixed by the dataset)
#define NCH   12
#define GD    160
#define GH    160
#define GW    160
#define GVOL  (GD * GH * GW)          // 4,096,000 voxels

// Interleaved channel-last fp16 grid: [D*H*W, 12] halfs = 24 B/voxel, 98.3 MB.
// +pad voxels: unconditional x0+1 read at last voxel (weight fx==0) and 64B
// aligned-window over-read. Zero-initialized .bss.
__device__ __align__(16) __half g_grid_h[((size_t)GVOL + 8) * NCH];

// ---------------------------------------------------------------------------
// Pass 1: transpose+convert [C, D, H, W] fp32 -> [D*H*W, C] fp16.
// One thread = TWO consecutive voxels (12x LDG.64 reads, 3x STG.128 writes).
// ---------------------------------------------------------------------------
__global__ void __launch_bounds__(256) convert_cl_kernel(const float* __restrict__ grid) {
    int t = blockIdx.x * blockDim.x + threadIdx.x;
    int v = t * 2;
    if (v >= GVOL) return;

    __half h[2 * NCH];
#pragma unroll
    for (int c = 0; c < NCH; c++) {
        float2 f = __ldcs(reinterpret_cast<const float2*>(grid + (size_t)c * GVOL + v));
        h[c]       = __float2half(f.x);
        h[NCH + c] = __float2half(f.y);
    }

    uint4* dst = reinterpret_cast<uint4*>(g_grid_h + (size_t)v * NCH);
    const uint4* s = reinterpret_cast<const uint4*>(h);
    dst[0] = s[0];
    dst[1] = s[1];
    dst[2] = s[2];
}

// ---------------------------------------------------------------------------
// Pass 2: trilinear sample, one thread per point, all 12 channels.
// Per corner-pair (48B at 8B alignment): 16B-aligned window gather of
// 3x LDG.128 (+1 predicated LDG.128 only when the pair straddles, sh==1).
// One pair in flight at a time -> ~52 live regs -> 6 CTAs of 192 threads
// (56% occ) to saturate the L1tex sector wall.
// ---------------------------------------------------------------------------
__device__ __forceinline__ float2 u2f2(unsigned u) {
    __half2 h = *reinterpret_cast<__half2*>(&u);
    return __half22float2(h);
}

__global__ void __launch_bounds__(192, 6) trilinear_sample_kernel(
    const float* __restrict__ xyz,
    const float* __restrict__ xyz_min,
    const float* __restrict__ xyz_max,
    float* __restrict__ out,
    int n)
{
    int i = blockIdx.x * blockDim.x + threadIdx.x;
    if (i >= n) return;

    float p0 = __ldcs(xyz + 3 * (size_t)i + 0);
    float p1 = __ldcs(xyz + 3 * (size_t)i + 1);
    float p2 = __ldcs(xyz + 3 * (size_t)i + 2);

    float mn0 = __ldg(xyz_min + 0), mn1 = __ldg(xyz_min + 1), mn2 = __ldg(xyz_min + 2);
    float mx0 = __ldg(xyz_max + 0), mx1 = __ldg(xyz_max + 1), mx2 = __ldg(xyz_max + 2);

    float u0 = (p0 - mn0) / (mx0 - mn0);
    float u1 = (p1 - mn1) / (mx1 - mn1);
    float u2 = (p2 - mn2) / (mx2 - mn2);

    // px indexes W (from u2), py indexes H (from u1), pz indexes D (from u0)
    float px = u2 * (float)(GW - 1);
    float py = u1 * (float)(GH - 1);
    float pz = u0 * (float)(GD - 1);

    float xf = floorf(px), yf = floorf(py), zf = floorf(pz);
    float fx = px - xf,    fy = py - yf,    fz = pz - zf;

    int x0 = min(max((int)xf, 0), GW - 1);
    int y0 = min(max((int)yf, 0), GH - 1);
    int z0 = min(max((int)zf, 0), GD - 1);
    int y1 = min(y0 + 1, GH - 1);
    int z1 = min(z0 + 1, GD - 1);

    float wx0 = 1.0f - fx, wx1 = fx;
    float wy0 = 1.0f - fy, wy1 = fy;
    float wz0 = 1.0f - fz, wz1 = fz;

    float wp[4];
    wp[0] = wz0 * wy0;
    wp[1] = wz0 * wy1;
    wp[2] = wz1 * wy0;
    wp[3] = wz1 * wy1;

    int vidx[4];
    vidx[0] = (z0 * GH + y0) * GW + x0;
    vidx[1] = (z0 * GH + y1) * GW + x0;
    vidx[2] = (z1 * GH + y0) * GW + x0;
    vidx[3] = (z1 * GH + y1) * GW + x0;

    const char* gbase = reinterpret_cast<const char*>(g_grid_h);

    float acc[NCH];
#pragma unroll
    for (int c = 0; c < NCH; c++) acc[c] = 0.0f;

#pragma unroll
    for (int p = 0; p < 4; p++) {
        int B = vidx[p] * 24;                    // byte offset; B mod 16 in {0,8}
        const uint4* q = reinterpret_cast<const uint4*>(gbase + (B & ~15));
        bool sh = (B & 8) != 0;

        uint4 W0 = __ldg(q + 0);
        uint4 W1 = __ldg(q + 1);
        uint4 W2 = __ldg(q + 2);
        uint4 W3 = make_uint4(0u, 0u, 0u, 0u);
        if (sh) W3 = __ldg(q + 3);               // predicated: no wavefronts when off

        float w0 = wp[p] * wx0;
        float w1 = wp[p] * wx1;

        unsigned wd[16];
        wd[0]  = W0.x; wd[1]  = W0.y; wd[2]  = W0.z; wd[3]  = W0.w;
        wd[4]  = W1.x; wd[5]  = W1.y; wd[6]  = W1.z; wd[7]  = W1.w;
        wd[8]  = W2.x; wd[9]  = W2.y; wd[10] = W2.z; wd[11] = W2.w;
        wd[12] = W3.x; wd[13] = W3.y; wd[14] = W3.z; wd[15] = W3.w;

        // Pair occupies wd[off .. off+11], off = sh ? 2 : 0.
        unsigned u[12];
#pragma unroll
        for (int k = 0; k < 12; k++)
            u[k] = sh ? wd[k + 2] : wd[k];

        // u[0..5] = x0 ch0-11 (half2 each), u[6..11] = x0+1 ch0-11
#pragma unroll
        for (int j = 0; j < 6; j++) {
            float2 a = u2f2(u[j]);
            float2 b = u2f2(u[6 + j]);
            acc[2*j]   = fmaf(w0, a.x, fmaf(w1, b.x, acc[2*j]));
            acc[2*j+1] = fmaf(w0, a.y, fmaf(w1, b.y, acc[2*j+1]));
        }
    }

    // out is [N, 12] row-major; 48B per thread -> 3x float4 streaming stores
    float4* o = reinterpret_cast<float4*>(out + (size_t)i * NCH);
    __stcs(o + 0, make_float4(acc[0], acc[1], acc[2],  acc[3]));
    __stcs(o + 1, make_float4(acc[4], acc[5], acc[6],  acc[7]));
    __stcs(o + 2, make_float4(acc[8], acc[9], acc[10], acc[11]));
}

extern "C" void kernel_launch(void* const* d_in, const int* in_sizes, int n_in,
                              void* d_out, int out_size) {
    const float* xyz     = (const float*)d_in[0];  // [N, 3]
    const float* grid    = (const float*)d_in[1];  // [1, 12, 160, 160, 160]
    const float* xyz_min = (const float*)d_in[2];  // [3]
    const float* xyz_max = (const float*)d_in[3];  // [3]
    float* out = (float*)d_out;                    // [N, 12]

    int n = in_sizes[0] / 3;

    {
        int blocks = (GVOL / 2 + 255) / 256;
        convert_cl_kernel<<<blocks, 256>>>(grid);
    }
    {
        int threads = 192;
        int blocks = (n + threads - 1) / threads;
        trilinear_sample_kernel<<<blocks, threads>>>(xyz, xyz_min, xyz_max, out, n);
    }
}